// round 13
// baseline (speedup 1.0000x reference)
#include <cuda_runtime.h>
#include <cuda_bf16.h>
#include <cuda_fp16.h>
#include <cstdint>

#define DIM        128
#define MAX_NODES  100000
#define MAX_EDGES  800000
#define BUCKET_CAP 64

// ---------------------------------------------------------------------------
// Static device scratch (no allocations allowed)
// g_projh has one extra all-zero row at index MAX_NODES (gather pad target).
// ---------------------------------------------------------------------------
__device__ __half   g_projh[(size_t)(MAX_NODES + 1) * DIM];
__device__ uint32_t g_Whi[DIM * DIM / 2];               // fp16x2 [n][k/2]
__device__ int      g_cnt[MAX_NODES];                   // per-dst edge count
__device__ int      g_bucket[(size_t)MAX_NODES * BUCKET_CAP]; // src per dst

// ---------------------------------------------------------------------------
// helpers
// ---------------------------------------------------------------------------
__device__ __forceinline__ uint32_t smem_to_u32(const void* smem_ptr) {
    uint32_t addr;
    asm("{ .reg .u64 tmp; cvta.to.shared.u64 tmp, %1; cvt.u32.u64 %0, tmp; }"
        : "=r"(addr) : "l"(smem_ptr));
    return addr;
}

#define LDMATRIX_X4(r0, r1, r2, r3, addr) \
    asm volatile("ldmatrix.sync.aligned.m8n8.x4.shared.b16 {%0,%1,%2,%3}, [%4];" \
        : "=r"(r0), "=r"(r1), "=r"(r2), "=r"(r3) : "r"(addr))

#define MMA_F16(c, a, b) \
    asm volatile("mma.sync.aligned.m16n8k16.row.col.f32.f16.f16.f32 " \
        "{%0,%1,%2,%3}, {%4,%5,%6,%7}, {%8,%9}, {%0,%1,%2,%3};" \
        : "+f"((c)[0]), "+f"((c)[1]), "+f"((c)[2]), "+f"((c)[3]) \
        : "r"((a)[0]), "r"((a)[1]), "r"((a)[2]), "r"((a)[3]), \
          "r"((b)[0]), "r"((b)[1]))

__device__ __forceinline__ uint32_t pack_h2(float a, float b) {
    __half2 h = __floats2half2_rn(a, b);
    return *reinterpret_cast<uint32_t*>(&h);
}

// ---------------------------------------------------------------------------
// W precompute: W[n][k] fp32 -> fp16 packed pairs [n][k/2].
// Also zeroes the proj pad row (block 0).
// ---------------------------------------------------------------------------
__global__ void wprep_kernel(const float* __restrict__ W) {
    int idx = blockIdx.x * blockDim.x + threadIdx.x;      // 0..8191
    if (blockIdx.x == 0 && threadIdx.x < 64)
        reinterpret_cast<uint32_t*>(g_projh)[(size_t)MAX_NODES * 64 + threadIdx.x] = 0;
    if (idx >= DIM * DIM / 2) return;
    int n  = idx >> 6;
    int kp = idx & 63;
    float2 w = *reinterpret_cast<const float2*>(W + (size_t)n * DIM + kp * 2);
    g_Whi[idx] = pack_h2(w.x, w.y);
}

// ---------------------------------------------------------------------------
// Bucket fill: no scan needed. pos = atomicAdd(cnt[d]); bucket[d][pos] = src.
// Capacity 64 >> max degree for Poisson(8) data; clamp prevents OOB.
// ---------------------------------------------------------------------------
__global__ void fill_kernel(const int* __restrict__ src,
                            const int* __restrict__ dst, int E) {
    int base = (blockIdx.x * blockDim.x + threadIdx.x) * 4;
    if (base + 3 < E) {
        int4 s4 = *reinterpret_cast<const int4*>(src + base);
        int4 d4 = *reinterpret_cast<const int4*>(dst + base);
        int p;
        p = atomicAdd(&g_cnt[d4.x], 1);
        if (p < BUCKET_CAP) g_bucket[(size_t)d4.x * BUCKET_CAP + p] = s4.x;
        p = atomicAdd(&g_cnt[d4.y], 1);
        if (p < BUCKET_CAP) g_bucket[(size_t)d4.y * BUCKET_CAP + p] = s4.y;
        p = atomicAdd(&g_cnt[d4.z], 1);
        if (p < BUCKET_CAP) g_bucket[(size_t)d4.z * BUCKET_CAP + p] = s4.z;
        p = atomicAdd(&g_cnt[d4.w], 1);
        if (p < BUCKET_CAP) g_bucket[(size_t)d4.w * BUCKET_CAP + p] = s4.w;
    } else {
        for (int e = base; e < E; e++) {
            int p = atomicAdd(&g_cnt[dst[e]], 1);
            if (p < BUCKET_CAP) g_bucket[(size_t)dst[e] * BUCKET_CAP + p] = src[e];
        }
    }
}

// ---------------------------------------------------------------------------
// GEMM: proj = relu(h @ W^T) -> fp16. Single-pass fp16 HMMA, fp32 accum.
//   CTA: 128 rows x 128 out x 128 k, 8 warps = 2(m) x 4(n), warp tile 64x32.
// ---------------------------------------------------------------------------
#define LDB 136
#define ROWB (LDB * 2)
#define GEMM_SMEM (128 * ROWB)     // 34816 bytes

__global__ __launch_bounds__(256, 2)
void gemm_relu_hmma_kernel(const float* __restrict__ h, int N)
{
    extern __shared__ char smem[];
    const uint32_t sbase = smem_to_u32(smem);
    const int tid  = threadIdx.x;
    const int lane = tid & 31;
    const int wid  = tid >> 5;
    const int warp_m = wid & 1;
    const int warp_n = wid >> 1;
    const int rowBase = blockIdx.x * 128;

    // ---- stage h tile as fp16 ----
    {
        const int r     = tid >> 1;
        const int cbase = (tid & 1) * 64;
        const int gr    = rowBase + r;
        const float4* hsrc = reinterpret_cast<const float4*>(
            h + (size_t)gr * DIM + cbase);
        char* dst16 = smem + r * ROWB + cbase * 2;
        #pragma unroll
        for (int q = 0; q < 16; q++) {
            float4 v = (gr < N) ? hsrc[q] : make_float4(0.f, 0.f, 0.f, 0.f);
            *reinterpret_cast<uint2*>(dst16 + q * 8) =
                make_uint2(pack_h2(v.x, v.y), pack_h2(v.z, v.w));
        }
    }
    __syncthreads();

    float acc[4][4][4];
    #pragma unroll
    for (int mi = 0; mi < 4; mi++)
        #pragma unroll
        for (int ni = 0; ni < 4; ni++)
            #pragma unroll
            for (int r = 0; r < 4; r++)
                acc[mi][ni][r] = 0.0f;

    const int lrow = lane & 15;
    const int lk8  = (lane >> 4) << 3;
    const uint32_t wrowoff =
        (uint32_t)(warp_n * 32 + (lane >> 2)) * 64 + (lane & 3);

    #pragma unroll
    for (int ks = 0; ks < 8; ks++) {
        const int k0 = ks * 16;
        uint32_t a[4][4];
        #pragma unroll
        for (int mi = 0; mi < 4; mi++) {
            uint32_t addr = sbase
                + (uint32_t)(warp_m * 64 + mi * 16 + lrow) * ROWB
                + (uint32_t)(k0 + lk8) * 2;
            LDMATRIX_X4(a[mi][0], a[mi][1], a[mi][2], a[mi][3], addr);
        }
        #pragma unroll
        for (int ni = 0; ni < 4; ni++) {
            const uint32_t* wrow = g_Whi + wrowoff + (uint32_t)ni * 8 * 64;
            uint32_t b[2];
            b[0] = wrow[ks * 8];
            b[1] = wrow[ks * 8 + 4];
            #pragma unroll
            for (int mi = 0; mi < 4; mi++)
                MMA_F16(acc[mi][ni], a[mi], b);
        }
    }

    // ---- epilogue: ReLU + fp16 store ----
    const int erow = lane >> 2;
    const int ecol = (lane & 3) * 2;
    #pragma unroll
    for (int mi = 0; mi < 4; mi++) {
        const int row0 = rowBase + warp_m * 64 + mi * 16 + erow;
        #pragma unroll
        for (int ni = 0; ni < 4; ni++) {
            const int col = warp_n * 32 + ni * 8 + ecol;
            if (row0 < N) {
                __half2 hv = __floats2half2_rn(fmaxf(acc[mi][ni][0], 0.0f),
                                               fmaxf(acc[mi][ni][1], 0.0f));
                *reinterpret_cast<__half2*>(
                    g_projh + (size_t)row0 * DIM + col) = hv;
            }
            if (row0 + 8 < N) {
                __half2 hv = __floats2half2_rn(fmaxf(acc[mi][ni][2], 0.0f),
                                               fmaxf(acc[mi][ni][3], 0.0f));
                *reinterpret_cast<__half2*>(
                    g_projh + (size_t)(row0 + 8) * DIM + col) = hv;
            }
        }
    }
}

// ---------------------------------------------------------------------------
// Persistent gather: out[d] = sum over bucket[d] of projh[src]
// 16 lanes per dst (uint4 = 8 fp16 per lane). Index loads coalesced by the
// low 8 lanes of each group, broadcast via shfl. 8 rows in flight (MLP=8);
// indices past count clamp to the all-zero pad row (L1-hot, nearly free).
// ---------------------------------------------------------------------------
__device__ __forceinline__ void acc_row(float acc[8], uint4 r) {
    const __half2* hp = reinterpret_cast<const __half2*>(&r);
    #pragma unroll
    for (int j = 0; j < 4; j++) {
        float2 f = __half22float2(hp[j]);
        acc[j * 2 + 0] += f.x;
        acc[j * 2 + 1] += f.y;
    }
}

#define GATHER_BLOCKS 1184   // 8 per SM x 148 SMs

__global__ __launch_bounds__(256)
void gather_kernel(float* __restrict__ out, int N)
{
    const int l16    = threadIdx.x & 15;
    const int l8     = l16 & 7;
    const int grp0   = (blockIdx.x * blockDim.x + threadIdx.x) >> 4;
    const int stride = (GATHER_BLOCKS * 256) >> 4;

    const uint4* projv = reinterpret_cast<const uint4*>(g_projh) + l16;

    for (int d = grp0; d < N; d += stride) {
        int c = __ldg(&g_cnt[d]);
        if (c > BUCKET_CAP) c = BUCKET_CAP;
        const int* bkt = g_bucket + (size_t)d * BUCKET_CAP;

        float acc[8];
        #pragma unroll
        for (int j = 0; j < 8; j++) acc[j] = 0.0f;

        for (int i = 0; i < c; i += 8) {
            const int li = i + l8;
            const int myidx = (li < c) ? __ldg(&bkt[li]) : MAX_NODES;
            uint4 r[8];
            #pragma unroll
            for (int j = 0; j < 8; j++) {
                int s = __shfl_sync(0xFFFFFFFFu, myidx, j, 16);
                r[j] = __ldg(&projv[(size_t)s * 16]);
            }
            #pragma unroll
            for (int j = 0; j < 8; j++)
                acc_row(acc, r[j]);
        }

        float* op = out + (size_t)d * DIM + l16 * 8;
        __stcs(reinterpret_cast<float4*>(op),
               make_float4(acc[0], acc[1], acc[2], acc[3]));
        __stcs(reinterpret_cast<float4*>(op + 4),
               make_float4(acc[4], acc[5], acc[6], acc[7]));
    }
}

// ---------------------------------------------------------------------------
// Launch: s2 runs wprep(+pad zero) + GEMM; stream 0 runs memset + bucket fill.
// ---------------------------------------------------------------------------
extern "C" void kernel_launch(void* const* d_in, const int* in_sizes, int n_in,
                              void* d_out, int out_size)
{
    const float* h   = (const float*)d_in[0];
    const float* W   = (const float*)d_in[1];
    const int*   src = (const int*)d_in[2];
    const int*   dst = (const int*)d_in[3];
    float*       out = (float*)d_out;

    const int N = in_sizes[0] / DIM;
    const int E = in_sizes[2];

    static cudaStream_t s2 = nullptr;
    static cudaEvent_t evFork = nullptr, evJoin = nullptr;
    if (!s2) {
        cudaStreamCreateWithFlags(&s2, cudaStreamNonBlocking);
        cudaEventCreateWithFlags(&evFork, cudaEventDisableTiming);
        cudaEventCreateWithFlags(&evJoin, cudaEventDisableTiming);
        cudaFuncSetAttribute(gemm_relu_hmma_kernel,
                             cudaFuncAttributeMaxDynamicSharedMemorySize,
                             GEMM_SMEM);
    }

    // ---- fork immediately: s2 = wprep(+pad zero) + GEMM ----
    cudaEventRecord(evFork, 0);
    cudaStreamWaitEvent(s2, evFork, 0);

    wprep_kernel<<<32, 256, 0, s2>>>(W);
    gemm_relu_hmma_kernel<<<(N + 127) / 128, 256, GEMM_SMEM, s2>>>(h, N);

    // ---- stream 0: zero counters + bucket fill (no scan needed) ----
    void* cntPtr = nullptr;
    cudaGetSymbolAddress(&cntPtr, g_cnt);
    cudaMemsetAsync(cntPtr, 0, (size_t)N * sizeof(int), 0);
    fill_kernel<<<(E / 4 + 255) / 256 + 1, 256>>>(src, dst, E);

    // ---- join ----
    cudaEventRecord(evJoin, s2);
    cudaStreamWaitEvent(0, evJoin, 0);

    // Persistent gather
    gather_kernel<<<GATHER_BLOCKS, 256>>>(out, N);
}

// round 14
// speedup vs baseline: 1.2008x; 1.2008x over previous
#include <cuda_runtime.h>
#include <cuda_bf16.h>
#include <cuda_fp16.h>
#include <cstdint>

#define DIM        128
#define MAX_NODES  100000
#define MAX_EDGES  800000

// ---------------------------------------------------------------------------
// Static device scratch (no allocations allowed)
// g_projh has one extra all-zero row at index MAX_NODES (gather pad target).
// ---------------------------------------------------------------------------
__device__ __half   g_projh[(size_t)(MAX_NODES + 1) * DIM];
__device__ uint32_t g_Whi[DIM * DIM / 2];               // fp16x2 [n][k/2]
__device__ int      g_cnt[MAX_NODES];                   // degree, then cursor
__device__ int      g_off[MAX_NODES + 1];               // CSR offsets (by dst)
__device__ int      g_bsum[128];                        // scan block sums
__device__ int      g_esrc[MAX_EDGES];                  // src grouped by dst

// ---------------------------------------------------------------------------
// helpers
// ---------------------------------------------------------------------------
__device__ __forceinline__ uint32_t smem_to_u32(const void* smem_ptr) {
    uint32_t addr;
    asm("{ .reg .u64 tmp; cvta.to.shared.u64 tmp, %1; cvt.u32.u64 %0, tmp; }"
        : "=r"(addr) : "l"(smem_ptr));
    return addr;
}

#define LDMATRIX_X4(r0, r1, r2, r3, addr) \
    asm volatile("ldmatrix.sync.aligned.m8n8.x4.shared.b16 {%0,%1,%2,%3}, [%4];" \
        : "=r"(r0), "=r"(r1), "=r"(r2), "=r"(r3) : "r"(addr))

#define MMA_F16(c, a, b) \
    asm volatile("mma.sync.aligned.m16n8k16.row.col.f32.f16.f16.f32 " \
        "{%0,%1,%2,%3}, {%4,%5,%6,%7}, {%8,%9}, {%0,%1,%2,%3};" \
        : "+f"((c)[0]), "+f"((c)[1]), "+f"((c)[2]), "+f"((c)[3]) \
        : "r"((a)[0]), "r"((a)[1]), "r"((a)[2]), "r"((a)[3]), \
          "r"((b)[0]), "r"((b)[1]))

__device__ __forceinline__ uint32_t pack_h2(float a, float b) {
    __half2 h = __floats2half2_rn(a, b);
    return *reinterpret_cast<uint32_t*>(&h);
}

// ---------------------------------------------------------------------------
// W precompute: W[n][k] fp32 -> fp16 packed pairs [n][k/2].
// Also zeroes the proj pad row (block 0).
// ---------------------------------------------------------------------------
__global__ void wprep_kernel(const float* __restrict__ W) {
    int idx = blockIdx.x * blockDim.x + threadIdx.x;      // 0..8191
    if (blockIdx.x == 0 && threadIdx.x < 64)
        reinterpret_cast<uint32_t*>(g_projh)[(size_t)MAX_NODES * 64 + threadIdx.x] = 0;
    if (idx >= DIM * DIM / 2) return;
    int n  = idx >> 6;
    int kp = idx & 63;
    float2 w = *reinterpret_cast<const float2*>(W + (size_t)n * DIM + kp * 2);
    g_Whi[idx] = pack_h2(w.x, w.y);
}

// ---------------------------------------------------------------------------
// CSR build: histogram -> scan -> fill (hist/fill vectorized 4 edges/thread)
// ---------------------------------------------------------------------------
__global__ void hist_kernel(const int* __restrict__ dst, int E) {
    int base = (blockIdx.x * blockDim.x + threadIdx.x) * 4;
    if (base + 3 < E) {
        int4 d4 = *reinterpret_cast<const int4*>(dst + base);
        atomicAdd(&g_cnt[d4.x], 1);
        atomicAdd(&g_cnt[d4.y], 1);
        atomicAdd(&g_cnt[d4.z], 1);
        atomicAdd(&g_cnt[d4.w], 1);
    } else {
        for (int e = base; e < E; e++) atomicAdd(&g_cnt[dst[e]], 1);
    }
}

#define SCAN_BLK 1024
__global__ void scan_reduce_kernel(int N) {
    __shared__ int sdata[256];
    const int t    = threadIdx.x;
    const int base = blockIdx.x * SCAN_BLK;
    int s = 0;
    #pragma unroll
    for (int q = 0; q < 4; q++) {
        int i = base + t * 4 + q;
        if (i < N) s += g_cnt[i];
    }
    sdata[t] = s;
    __syncthreads();
    #pragma unroll
    for (int o = 128; o > 0; o >>= 1) {
        if (t < o) sdata[t] += sdata[t + o];
        __syncthreads();
    }
    if (t == 0) g_bsum[blockIdx.x] = sdata[0];
}

__global__ void scan_write_kernel(int N, int E) {
    __shared__ int ssum[256];
    __shared__ int sb[128];
    __shared__ int sbase;
    const int b = blockIdx.x, t = threadIdx.x;
    if (t < gridDim.x && t < 128) sb[t] = g_bsum[t];
    __syncthreads();
    if (t == 0) {
        int a = 0;
        for (int j = 0; j < b; j++) a += sb[j];
        sbase = a;
        if (b == 0) g_off[N] = E;
    }
    const int base = b * SCAN_BLK;
    int v[4];
    int local = 0;
    #pragma unroll
    for (int q = 0; q < 4; q++) {
        int i = base + t * 4 + q;
        v[q] = (i < N) ? g_cnt[i] : 0;
        local += v[q];
    }
    ssum[t] = local;
    __syncthreads();
    for (int o = 1; o < 256; o <<= 1) {
        int x = (t >= o) ? ssum[t - o] : 0;
        __syncthreads();
        ssum[t] += x;
        __syncthreads();
    }
    int excl = sbase + ssum[t] - local;
    #pragma unroll
    for (int q = 0; q < 4; q++) {
        int i = base + t * 4 + q;
        if (i < N) { g_off[i] = excl; g_cnt[i] = excl; }   // g_cnt becomes cursor
        excl += v[q];
    }
}

__global__ void fill_kernel(const int* __restrict__ src,
                            const int* __restrict__ dst, int E) {
    int base = (blockIdx.x * blockDim.x + threadIdx.x) * 4;
    if (base + 3 < E) {
        int4 s4 = *reinterpret_cast<const int4*>(src + base);
        int4 d4 = *reinterpret_cast<const int4*>(dst + base);
        int p;
        p = atomicAdd(&g_cnt[d4.x], 1); g_esrc[p] = s4.x;
        p = atomicAdd(&g_cnt[d4.y], 1); g_esrc[p] = s4.y;
        p = atomicAdd(&g_cnt[d4.z], 1); g_esrc[p] = s4.z;
        p = atomicAdd(&g_cnt[d4.w], 1); g_esrc[p] = s4.w;
    } else {
        for (int e = base; e < E; e++) {
            int p = atomicAdd(&g_cnt[dst[e]], 1);
            g_esrc[p] = src[e];
        }
    }
}

// ---------------------------------------------------------------------------
// GEMM: proj = relu(h @ W^T) -> fp16. Single-pass fp16 HMMA, fp32 accum.
//   CTA: 128 rows x 128 out x 128 k, 8 warps = 2(m) x 4(n), warp tile 64x32.
// ---------------------------------------------------------------------------
#define LDB 136
#define ROWB (LDB * 2)
#define GEMM_SMEM (128 * ROWB)     // 34816 bytes

__global__ __launch_bounds__(256, 2)
void gemm_relu_hmma_kernel(const float* __restrict__ h, int N)
{
    extern __shared__ char smem[];
    const uint32_t sbase = smem_to_u32(smem);
    const int tid  = threadIdx.x;
    const int lane = tid & 31;
    const int wid  = tid >> 5;
    const int warp_m = wid & 1;
    const int warp_n = wid >> 1;
    const int rowBase = blockIdx.x * 128;

    // ---- stage h tile as fp16 ----
    {
        const int r     = tid >> 1;
        const int cbase = (tid & 1) * 64;
        const int gr    = rowBase + r;
        const float4* hsrc = reinterpret_cast<const float4*>(
            h + (size_t)gr * DIM + cbase);
        char* dst16 = smem + r * ROWB + cbase * 2;
        #pragma unroll
        for (int q = 0; q < 16; q++) {
            float4 v = (gr < N) ? hsrc[q] : make_float4(0.f, 0.f, 0.f, 0.f);
            *reinterpret_cast<uint2*>(dst16 + q * 8) =
                make_uint2(pack_h2(v.x, v.y), pack_h2(v.z, v.w));
        }
    }
    __syncthreads();

    float acc[4][4][4];
    #pragma unroll
    for (int mi = 0; mi < 4; mi++)
        #pragma unroll
        for (int ni = 0; ni < 4; ni++)
            #pragma unroll
            for (int r = 0; r < 4; r++)
                acc[mi][ni][r] = 0.0f;

    const int lrow = lane & 15;
    const int lk8  = (lane >> 4) << 3;
    const uint32_t wrowoff =
        (uint32_t)(warp_n * 32 + (lane >> 2)) * 64 + (lane & 3);

    #pragma unroll
    for (int ks = 0; ks < 8; ks++) {
        const int k0 = ks * 16;
        uint32_t a[4][4];
        #pragma unroll
        for (int mi = 0; mi < 4; mi++) {
            uint32_t addr = sbase
                + (uint32_t)(warp_m * 64 + mi * 16 + lrow) * ROWB
                + (uint32_t)(k0 + lk8) * 2;
            LDMATRIX_X4(a[mi][0], a[mi][1], a[mi][2], a[mi][3], addr);
        }
        #pragma unroll
        for (int ni = 0; ni < 4; ni++) {
            const uint32_t* wrow = g_Whi + wrowoff + (uint32_t)ni * 8 * 64;
            uint32_t b[2];
            b[0] = wrow[ks * 8];
            b[1] = wrow[ks * 8 + 4];
            #pragma unroll
            for (int mi = 0; mi < 4; mi++)
                MMA_F16(acc[mi][ni], a[mi], b);
        }
    }

    // ---- epilogue: ReLU + fp16 store ----
    const int erow = lane >> 2;
    const int ecol = (lane & 3) * 2;
    #pragma unroll
    for (int mi = 0; mi < 4; mi++) {
        const int row0 = rowBase + warp_m * 64 + mi * 16 + erow;
        #pragma unroll
        for (int ni = 0; ni < 4; ni++) {
            const int col = warp_n * 32 + ni * 8 + ecol;
            if (row0 < N) {
                __half2 hv = __floats2half2_rn(fmaxf(acc[mi][ni][0], 0.0f),
                                               fmaxf(acc[mi][ni][1], 0.0f));
                *reinterpret_cast<__half2*>(
                    g_projh + (size_t)row0 * DIM + col) = hv;
            }
            if (row0 + 8 < N) {
                __half2 hv = __floats2half2_rn(fmaxf(acc[mi][ni][2], 0.0f),
                                               fmaxf(acc[mi][ni][3], 0.0f));
                *reinterpret_cast<__half2*>(
                    g_projh + (size_t)(row0 + 8) * DIM + col) = hv;
            }
        }
    }
}

// ---------------------------------------------------------------------------
// Persistent gather: out[d] = sum over CSR bucket of projh[src]
// 16 lanes per dst (uint4 = 8 fp16 per lane). The gather is ISSUE-bound
// (ncu: fma 26%, L2 15%), so accumulation uses a 2-level fp16 pairwise tree
// (hadd2) before converting to fp32: 128 -> 56 arith ops per 8 rows.
// Indices past end clamp to the all-zero pad row (L1-hot, free in the tree).
// ---------------------------------------------------------------------------
#define GATHER_BLOCKS 1184   // 8 per SM x 148 SMs

__device__ __forceinline__ void hadd2_4(__half2 o[4], const uint4& a,
                                        const uint4& b) {
    const __half2* pa = reinterpret_cast<const __half2*>(&a);
    const __half2* pb = reinterpret_cast<const __half2*>(&b);
    #pragma unroll
    for (int j = 0; j < 4; j++) o[j] = __hadd2(pa[j], pb[j]);
}

__global__ __launch_bounds__(256)
void gather_kernel(float* __restrict__ out, int N)
{
    const int l16    = threadIdx.x & 15;
    const int grp0   = (blockIdx.x * blockDim.x + threadIdx.x) >> 4;
    const int stride = (GATHER_BLOCKS * 256) >> 4;

    const uint4* projv = reinterpret_cast<const uint4*>(g_projh) + l16;

    for (int d = grp0; d < N; d += stride) {
        const int start = __ldg(&g_off[d]);
        const int end   = __ldg(&g_off[d + 1]);

        float acc[8];
        #pragma unroll
        for (int j = 0; j < 8; j++) acc[j] = 0.0f;

        for (int i = start; i < end; i += 8) {
            int idx[8];
            #pragma unroll
            for (int j = 0; j < 8; j++)
                idx[j] = (i + j < end) ? __ldg(&g_esrc[i + j]) : MAX_NODES;
            uint4 r[8];
            #pragma unroll
            for (int j = 0; j < 8; j++)
                r[j] = __ldg(&projv[(size_t)idx[j] * 16]);

            // level 1: 4 pair sums (fp16)
            __half2 p01[4], p23[4], p45[4], p67[4];
            hadd2_4(p01, r[0], r[1]);
            hadd2_4(p23, r[2], r[3]);
            hadd2_4(p45, r[4], r[5]);
            hadd2_4(p67, r[6], r[7]);
            // level 2: 2 quad sums (fp16)
            __half2 q03[4], q47[4];
            #pragma unroll
            for (int j = 0; j < 4; j++) {
                q03[j] = __hadd2(p01[j], p23[j]);
                q47[j] = __hadd2(p45[j], p67[j]);
            }
            // convert to fp32 and accumulate
            #pragma unroll
            for (int j = 0; j < 4; j++) {
                float2 f0 = __half22float2(q03[j]);
                float2 f1 = __half22float2(q47[j]);
                acc[j * 2 + 0] += f0.x + f1.x;
                acc[j * 2 + 1] += f0.y + f1.y;
            }
        }

        float* op = out + (size_t)d * DIM + l16 * 8;
        __stcs(reinterpret_cast<float4*>(op),
               make_float4(acc[0], acc[1], acc[2], acc[3]));
        __stcs(reinterpret_cast<float4*>(op + 4),
               make_float4(acc[4], acc[5], acc[6], acc[7]));
    }
}

// ---------------------------------------------------------------------------
// Launch: s2 runs wprep(+pad zero) + GEMM; stream 0 runs CSR build.
// ---------------------------------------------------------------------------
extern "C" void kernel_launch(void* const* d_in, const int* in_sizes, int n_in,
                              void* d_out, int out_size)
{
    const float* h   = (const float*)d_in[0];
    const float* W   = (const float*)d_in[1];
    const int*   src = (const int*)d_in[2];
    const int*   dst = (const int*)d_in[3];
    float*       out = (float*)d_out;

    const int N = in_sizes[0] / DIM;
    const int E = in_sizes[2];

    static cudaStream_t s2 = nullptr;
    static cudaEvent_t evFork = nullptr, evJoin = nullptr;
    if (!s2) {
        cudaStreamCreateWithFlags(&s2, cudaStreamNonBlocking);
        cudaEventCreateWithFlags(&evFork, cudaEventDisableTiming);
        cudaEventCreateWithFlags(&evJoin, cudaEventDisableTiming);
        cudaFuncSetAttribute(gemm_relu_hmma_kernel,
                             cudaFuncAttributeMaxDynamicSharedMemorySize,
                             GEMM_SMEM);
    }

    // ---- fork immediately: s2 = wprep(+pad zero) + GEMM ----
    cudaEventRecord(evFork, 0);
    cudaStreamWaitEvent(s2, evFork, 0);

    wprep_kernel<<<32, 256, 0, s2>>>(W);
    gemm_relu_hmma_kernel<<<(N + 127) / 128, 256, GEMM_SMEM, s2>>>(h, N);

    // ---- stream 0: CSR build ----
    void* cntPtr = nullptr;
    cudaGetSymbolAddress(&cntPtr, g_cnt);
    cudaMemsetAsync(cntPtr, 0, (size_t)N * sizeof(int), 0);

    hist_kernel<<<(E / 4 + 255) / 256 + 1, 256>>>(dst, E);
    const int NB = (N + SCAN_BLK - 1) / SCAN_BLK;
    scan_reduce_kernel<<<NB, 256>>>(N);
    scan_write_kernel<<<NB, 256>>>(N, E);
    fill_kernel<<<(E / 4 + 255) / 256 + 1, 256>>>(src, dst, E);

    // ---- join ----
    cudaEventRecord(evJoin, s2);
    cudaStreamWaitEvent(0, evJoin, 0);

    // Persistent gather (issue-optimized)
    gather_kernel<<<GATHER_BLOCKS, 256>>>(out, N);
}

// round 15
// speedup vs baseline: 1.2083x; 1.0063x over previous
#include <cuda_runtime.h>
#include <cuda_bf16.h>
#include <cuda_fp16.h>
#include <cstdint>

#define DIM        128
#define MAX_NODES  100000
#define MAX_EDGES  800000

// ---------------------------------------------------------------------------
// Static device scratch (no allocations allowed)
// g_projh has one extra all-zero row at index MAX_NODES (gather pad target).
// ---------------------------------------------------------------------------
__device__ __half   g_projh[(size_t)(MAX_NODES + 1) * DIM];
__device__ uint32_t g_Whi[DIM * DIM / 2];               // fp16x2 [n][k/2]
__device__ int      g_cnt[MAX_NODES];                   // degree, then cursor
__device__ int      g_off[MAX_NODES + 1];               // CSR offsets (by dst)
__device__ int      g_bsum[128];                        // scan block sums
__device__ int      g_esrc[MAX_EDGES];                  // src grouped by dst

// ---------------------------------------------------------------------------
// helpers
// ---------------------------------------------------------------------------
__device__ __forceinline__ uint32_t smem_to_u32(const void* smem_ptr) {
    uint32_t addr;
    asm("{ .reg .u64 tmp; cvta.to.shared.u64 tmp, %1; cvt.u32.u64 %0, tmp; }"
        : "=r"(addr) : "l"(smem_ptr));
    return addr;
}

#define LDMATRIX_X4(r0, r1, r2, r3, addr) \
    asm volatile("ldmatrix.sync.aligned.m8n8.x4.shared.b16 {%0,%1,%2,%3}, [%4];" \
        : "=r"(r0), "=r"(r1), "=r"(r2), "=r"(r3) : "r"(addr))

#define MMA_F16(c, a, b) \
    asm volatile("mma.sync.aligned.m16n8k16.row.col.f32.f16.f16.f32 " \
        "{%0,%1,%2,%3}, {%4,%5,%6,%7}, {%8,%9}, {%0,%1,%2,%3};" \
        : "+f"((c)[0]), "+f"((c)[1]), "+f"((c)[2]), "+f"((c)[3]) \
        : "r"((a)[0]), "r"((a)[1]), "r"((a)[2]), "r"((a)[3]), \
          "r"((b)[0]), "r"((b)[1]))

__device__ __forceinline__ uint32_t pack_h2(float a, float b) {
    __half2 h = __floats2half2_rn(a, b);
    return *reinterpret_cast<uint32_t*>(&h);
}

// ---------------------------------------------------------------------------
// W precompute: W[n][k] fp32 -> fp16 packed pairs [n][k/2].
// Also zeroes the proj pad row (block 0).
// ---------------------------------------------------------------------------
__global__ void wprep_kernel(const float* __restrict__ W) {
    int idx = blockIdx.x * blockDim.x + threadIdx.x;      // 0..8191
    if (blockIdx.x == 0 && threadIdx.x < 64)
        reinterpret_cast<uint32_t*>(g_projh)[(size_t)MAX_NODES * 64 + threadIdx.x] = 0;
    if (idx >= DIM * DIM / 2) return;
    int n  = idx >> 6;
    int kp = idx & 63;
    float2 w = *reinterpret_cast<const float2*>(W + (size_t)n * DIM + kp * 2);
    g_Whi[idx] = pack_h2(w.x, w.y);
}

// ---------------------------------------------------------------------------
// CSR build: histogram -> scan -> fill (hist/fill vectorized 4 edges/thread)
// ---------------------------------------------------------------------------
__global__ void hist_kernel(const int* __restrict__ dst, int E) {
    int base = (blockIdx.x * blockDim.x + threadIdx.x) * 4;
    if (base + 3 < E) {
        int4 d4 = *reinterpret_cast<const int4*>(dst + base);
        atomicAdd(&g_cnt[d4.x], 1);
        atomicAdd(&g_cnt[d4.y], 1);
        atomicAdd(&g_cnt[d4.z], 1);
        atomicAdd(&g_cnt[d4.w], 1);
    } else {
        for (int e = base; e < E; e++) atomicAdd(&g_cnt[dst[e]], 1);
    }
}

#define SCAN_BLK 1024
__global__ void scan_reduce_kernel(int N) {
    __shared__ int sdata[256];
    const int t    = threadIdx.x;
    const int base = blockIdx.x * SCAN_BLK;
    int s = 0;
    #pragma unroll
    for (int q = 0; q < 4; q++) {
        int i = base + t * 4 + q;
        if (i < N) s += g_cnt[i];
    }
    sdata[t] = s;
    __syncthreads();
    #pragma unroll
    for (int o = 128; o > 0; o >>= 1) {
        if (t < o) sdata[t] += sdata[t + o];
        __syncthreads();
    }
    if (t == 0) g_bsum[blockIdx.x] = sdata[0];
}

__global__ void scan_write_kernel(int N, int E) {
    __shared__ int ssum[256];
    __shared__ int sb[128];
    __shared__ int sbase;
    const int b = blockIdx.x, t = threadIdx.x;
    if (t < gridDim.x && t < 128) sb[t] = g_bsum[t];
    __syncthreads();
    if (t == 0) {
        int a = 0;
        for (int j = 0; j < b; j++) a += sb[j];
        sbase = a;
        if (b == 0) g_off[N] = E;
    }
    const int base = b * SCAN_BLK;
    int v[4];
    int local = 0;
    #pragma unroll
    for (int q = 0; q < 4; q++) {
        int i = base + t * 4 + q;
        v[q] = (i < N) ? g_cnt[i] : 0;
        local += v[q];
    }
    ssum[t] = local;
    __syncthreads();
    for (int o = 1; o < 256; o <<= 1) {
        int x = (t >= o) ? ssum[t - o] : 0;
        __syncthreads();
        ssum[t] += x;
        __syncthreads();
    }
    int excl = sbase + ssum[t] - local;
    #pragma unroll
    for (int q = 0; q < 4; q++) {
        int i = base + t * 4 + q;
        if (i < N) { g_off[i] = excl; g_cnt[i] = excl; }   // g_cnt becomes cursor
        excl += v[q];
    }
}

__global__ void fill_kernel(const int* __restrict__ src,
                            const int* __restrict__ dst, int E) {
    int base = (blockIdx.x * blockDim.x + threadIdx.x) * 4;
    if (base + 3 < E) {
        int4 s4 = *reinterpret_cast<const int4*>(src + base);
        int4 d4 = *reinterpret_cast<const int4*>(dst + base);
        int p;
        p = atomicAdd(&g_cnt[d4.x], 1); g_esrc[p] = s4.x;
        p = atomicAdd(&g_cnt[d4.y], 1); g_esrc[p] = s4.y;
        p = atomicAdd(&g_cnt[d4.z], 1); g_esrc[p] = s4.z;
        p = atomicAdd(&g_cnt[d4.w], 1); g_esrc[p] = s4.w;
    } else {
        for (int e = base; e < E; e++) {
            int p = atomicAdd(&g_cnt[dst[e]], 1);
            g_esrc[p] = src[e];
        }
    }
}

// ---------------------------------------------------------------------------
// GEMM: proj = relu(h @ W^T) -> fp16. Single-pass fp16 HMMA, fp32 accum.
//   CTA: 128 rows x 128 out x 128 k, 8 warps = 2(m) x 4(n), warp tile 64x32.
// ---------------------------------------------------------------------------
#define LDB 136
#define ROWB (LDB * 2)
#define GEMM_SMEM (128 * ROWB)     // 34816 bytes

__global__ __launch_bounds__(256, 2)
void gemm_relu_hmma_kernel(const float* __restrict__ h, int N)
{
    extern __shared__ char smem[];
    const uint32_t sbase = smem_to_u32(smem);
    const int tid  = threadIdx.x;
    const int lane = tid & 31;
    const int wid  = tid >> 5;
    const int warp_m = wid & 1;
    const int warp_n = wid >> 1;
    const int rowBase = blockIdx.x * 128;

    // ---- stage h tile as fp16 ----
    {
        const int r     = tid >> 1;
        const int cbase = (tid & 1) * 64;
        const int gr    = rowBase + r;
        const float4* hsrc = reinterpret_cast<const float4*>(
            h + (size_t)gr * DIM + cbase);
        char* dst16 = smem + r * ROWB + cbase * 2;
        #pragma unroll
        for (int q = 0; q < 16; q++) {
            float4 v = (gr < N) ? hsrc[q] : make_float4(0.f, 0.f, 0.f, 0.f);
            *reinterpret_cast<uint2*>(dst16 + q * 8) =
                make_uint2(pack_h2(v.x, v.y), pack_h2(v.z, v.w));
        }
    }
    __syncthreads();

    float acc[4][4][4];
    #pragma unroll
    for (int mi = 0; mi < 4; mi++)
        #pragma unroll
        for (int ni = 0; ni < 4; ni++)
            #pragma unroll
            for (int r = 0; r < 4; r++)
                acc[mi][ni][r] = 0.0f;

    const int lrow = lane & 15;
    const int lk8  = (lane >> 4) << 3;
    const uint32_t wrowoff =
        (uint32_t)(warp_n * 32 + (lane >> 2)) * 64 + (lane & 3);

    #pragma unroll
    for (int ks = 0; ks < 8; ks++) {
        const int k0 = ks * 16;
        uint32_t a[4][4];
        #pragma unroll
        for (int mi = 0; mi < 4; mi++) {
            uint32_t addr = sbase
                + (uint32_t)(warp_m * 64 + mi * 16 + lrow) * ROWB
                + (uint32_t)(k0 + lk8) * 2;
            LDMATRIX_X4(a[mi][0], a[mi][1], a[mi][2], a[mi][3], addr);
        }
        #pragma unroll
        for (int ni = 0; ni < 4; ni++) {
            const uint32_t* wrow = g_Whi + wrowoff + (uint32_t)ni * 8 * 64;
            uint32_t b[2];
            b[0] = wrow[ks * 8];
            b[1] = wrow[ks * 8 + 4];
            #pragma unroll
            for (int mi = 0; mi < 4; mi++)
                MMA_F16(acc[mi][ni], a[mi], b);
        }
    }

    // ---- epilogue: ReLU + fp16 store ----
    const int erow = lane >> 2;
    const int ecol = (lane & 3) * 2;
    #pragma unroll
    for (int mi = 0; mi < 4; mi++) {
        const int row0 = rowBase + warp_m * 64 + mi * 16 + erow;
        #pragma unroll
        for (int ni = 0; ni < 4; ni++) {
            const int col = warp_n * 32 + ni * 8 + ecol;
            if (row0 < N) {
                __half2 hv = __floats2half2_rn(fmaxf(acc[mi][ni][0], 0.0f),
                                               fmaxf(acc[mi][ni][1], 0.0f));
                *reinterpret_cast<__half2*>(
                    g_projh + (size_t)row0 * DIM + col) = hv;
            }
            if (row0 + 8 < N) {
                __half2 hv = __floats2half2_rn(fmaxf(acc[mi][ni][2], 0.0f),
                                               fmaxf(acc[mi][ni][3], 0.0f));
                *reinterpret_cast<__half2*>(
                    g_projh + (size_t)(row0 + 8) * DIM + col) = hv;
            }
        }
    }
}

// ---------------------------------------------------------------------------
// Persistent gather: out[d] = sum over CSR bucket of projh[src]
// 16 lanes per dst (uint4 = 8 fp16 per lane). The gather is LATENCY-bound at
// low occupancy (ncu: occ 39%, regs 54, nothing saturated). Fix: unroll 4
// (not 8) + reg cap -> ~6 CTAs/SM (~75% occ); latency hiding via 2x warps.
// One fp16 pair-sum level before fp32 accumulation (max 1 fp16 add/element).
// Indices past end clamp to the all-zero pad row (L1-hot, nearly free).
// ---------------------------------------------------------------------------
#define GATHER_BLOCKS 1184   // 8 per SM x 148 SMs (6 resident, rest queue)

__device__ __forceinline__ void hadd2_4(__half2 o[4], const uint4& a,
                                        const uint4& b) {
    const __half2* pa = reinterpret_cast<const __half2*>(&a);
    const __half2* pb = reinterpret_cast<const __half2*>(&b);
    #pragma unroll
    for (int j = 0; j < 4; j++) o[j] = __hadd2(pa[j], pb[j]);
}

__global__ __launch_bounds__(256, 6)
void gather_kernel(float* __restrict__ out, int N)
{
    const int l16    = threadIdx.x & 15;
    const int grp0   = (blockIdx.x * blockDim.x + threadIdx.x) >> 4;
    const int stride = (GATHER_BLOCKS * 256) >> 4;

    const uint4* projv = reinterpret_cast<const uint4*>(g_projh) + l16;

    for (int d = grp0; d < N; d += stride) {
        const int start = __ldg(&g_off[d]);
        const int end   = __ldg(&g_off[d + 1]);

        float acc[8];
        #pragma unroll
        for (int j = 0; j < 8; j++) acc[j] = 0.0f;

        for (int i = start; i < end; i += 4) {
            int idx[4];
            #pragma unroll
            for (int j = 0; j < 4; j++)
                idx[j] = (i + j < end) ? __ldg(&g_esrc[i + j]) : MAX_NODES;
            uint4 r[4];
            #pragma unroll
            for (int j = 0; j < 4; j++)
                r[j] = __ldg(&projv[(size_t)idx[j] * 16]);

            // one fp16 pair-sum level, then fp32 accumulate
            __half2 p01[4], p23[4];
            hadd2_4(p01, r[0], r[1]);
            hadd2_4(p23, r[2], r[3]);
            #pragma unroll
            for (int j = 0; j < 4; j++) {
                float2 f0 = __half22float2(p01[j]);
                float2 f1 = __half22float2(p23[j]);
                acc[j * 2 + 0] += f0.x + f1.x;
                acc[j * 2 + 1] += f0.y + f1.y;
            }
        }

        float* op = out + (size_t)d * DIM + l16 * 8;
        __stcs(reinterpret_cast<float4*>(op),
               make_float4(acc[0], acc[1], acc[2], acc[3]));
        __stcs(reinterpret_cast<float4*>(op + 4),
               make_float4(acc[4], acc[5], acc[6], acc[7]));
    }
}

// ---------------------------------------------------------------------------
// Launch: s2 runs wprep(+pad zero) + GEMM; stream 0 runs CSR build.
// ---------------------------------------------------------------------------
extern "C" void kernel_launch(void* const* d_in, const int* in_sizes, int n_in,
                              void* d_out, int out_size)
{
    const float* h   = (const float*)d_in[0];
    const float* W   = (const float*)d_in[1];
    const int*   src = (const int*)d_in[2];
    const int*   dst = (const int*)d_in[3];
    float*       out = (float*)d_out;

    const int N = in_sizes[0] / DIM;
    const int E = in_sizes[2];

    static cudaStream_t s2 = nullptr;
    static cudaEvent_t evFork = nullptr, evJoin = nullptr;
    if (!s2) {
        cudaStreamCreateWithFlags(&s2, cudaStreamNonBlocking);
        cudaEventCreateWithFlags(&evFork, cudaEventDisableTiming);
        cudaEventCreateWithFlags(&evJoin, cudaEventDisableTiming);
        cudaFuncSetAttribute(gemm_relu_hmma_kernel,
                             cudaFuncAttributeMaxDynamicSharedMemorySize,
                             GEMM_SMEM);
    }

    // ---- fork immediately: s2 = wprep(+pad zero) + GEMM ----
    cudaEventRecord(evFork, 0);
    cudaStreamWaitEvent(s2, evFork, 0);

    wprep_kernel<<<32, 256, 0, s2>>>(W);
    gemm_relu_hmma_kernel<<<(N + 127) / 128, 256, GEMM_SMEM, s2>>>(h, N);

    // ---- stream 0: CSR build ----
    void* cntPtr = nullptr;
    cudaGetSymbolAddress(&cntPtr, g_cnt);
    cudaMemsetAsync(cntPtr, 0, (size_t)N * sizeof(int), 0);

    hist_kernel<<<(E / 4 + 255) / 256 + 1, 256>>>(dst, E);
    const int NB = (N + SCAN_BLK - 1) / SCAN_BLK;
    scan_reduce_kernel<<<NB, 256>>>(N);
    scan_write_kernel<<<NB, 256>>>(N, E);
    fill_kernel<<<(E / 4 + 255) / 256 + 1, 256>>>(src, dst, E);

    // ---- join ----
    cudaEventRecord(evJoin, s2);
    cudaStreamWaitEvent(0, evJoin, 0);

    // Persistent gather (occupancy-optimized)
    gather_kernel<<<GATHER_BLOCKS, 256>>>(out, N);
}

// round 16
// speedup vs baseline: 1.3167x; 1.0897x over previous
#include <cuda_runtime.h>
#include <cuda_bf16.h>
#include <cuda_fp16.h>
#include <cstdint>

#define DIM        128
#define MAX_NODES  100000
#define MAX_EDGES  800000

// ---------------------------------------------------------------------------
// Static device scratch (no allocations allowed)
// g_projh has one extra all-zero row at index MAX_NODES (gather pad target).
// g_cnt relies on static zero-init for the FIRST call; the gather kernel
// re-zeroes it at the end of every call (self-cleaning, deterministic).
// ---------------------------------------------------------------------------
__device__ __half   g_projh[(size_t)(MAX_NODES + 1) * DIM];
__device__ uint32_t g_Whi[DIM * DIM / 2];               // fp16x2 [n][k/2]
__device__ int      g_cnt[MAX_NODES];                   // degree, then cursor
__device__ int      g_off[MAX_NODES + 1];               // CSR offsets (by dst)
__device__ int      g_bsum[128];                        // scan block sums
__device__ int      g_esrc[MAX_EDGES];                  // src grouped by dst

// ---------------------------------------------------------------------------
// helpers
// ---------------------------------------------------------------------------
__device__ __forceinline__ uint32_t smem_to_u32(const void* smem_ptr) {
    uint32_t addr;
    asm("{ .reg .u64 tmp; cvta.to.shared.u64 tmp, %1; cvt.u32.u64 %0, tmp; }"
        : "=r"(addr) : "l"(smem_ptr));
    return addr;
}

#define LDMATRIX_X4(r0, r1, r2, r3, addr) \
    asm volatile("ldmatrix.sync.aligned.m8n8.x4.shared.b16 {%0,%1,%2,%3}, [%4];" \
        : "=r"(r0), "=r"(r1), "=r"(r2), "=r"(r3) : "r"(addr))

#define MMA_F16(c, a, b) \
    asm volatile("mma.sync.aligned.m16n8k16.row.col.f32.f16.f16.f32 " \
        "{%0,%1,%2,%3}, {%4,%5,%6,%7}, {%8,%9}, {%0,%1,%2,%3};" \
        : "+f"((c)[0]), "+f"((c)[1]), "+f"((c)[2]), "+f"((c)[3]) \
        : "r"((a)[0]), "r"((a)[1]), "r"((a)[2]), "r"((a)[3]), \
          "r"((b)[0]), "r"((b)[1]))

__device__ __forceinline__ uint32_t pack_h2(float a, float b) {
    __half2 h = __floats2half2_rn(a, b);
    return *reinterpret_cast<uint32_t*>(&h);
}

// ---------------------------------------------------------------------------
// W precompute: W[n][k] fp32 -> fp16 packed pairs [n][k/2].
// Also zeroes the proj pad row (block 0).
// ---------------------------------------------------------------------------
__global__ void wprep_kernel(const float* __restrict__ W) {
    int idx = blockIdx.x * blockDim.x + threadIdx.x;      // 0..8191
    if (blockIdx.x == 0 && threadIdx.x < 64)
        reinterpret_cast<uint32_t*>(g_projh)[(size_t)MAX_NODES * 64 + threadIdx.x] = 0;
    if (idx >= DIM * DIM / 2) return;
    int n  = idx >> 6;
    int kp = idx & 63;
    float2 w = *reinterpret_cast<const float2*>(W + (size_t)n * DIM + kp * 2);
    g_Whi[idx] = pack_h2(w.x, w.y);
}

// ---------------------------------------------------------------------------
// CSR build: histogram -> scan -> fill (hist/fill vectorized 4 edges/thread)
// ---------------------------------------------------------------------------
__global__ void hist_kernel(const int* __restrict__ dst, int E) {
    int base = (blockIdx.x * blockDim.x + threadIdx.x) * 4;
    if (base + 3 < E) {
        int4 d4 = *reinterpret_cast<const int4*>(dst + base);
        atomicAdd(&g_cnt[d4.x], 1);
        atomicAdd(&g_cnt[d4.y], 1);
        atomicAdd(&g_cnt[d4.z], 1);
        atomicAdd(&g_cnt[d4.w], 1);
    } else {
        for (int e = base; e < E; e++) atomicAdd(&g_cnt[dst[e]], 1);
    }
}

#define SCAN_BLK 1024
__global__ void scan_reduce_kernel(int N) {
    __shared__ int sdata[256];
    const int t    = threadIdx.x;
    const int base = blockIdx.x * SCAN_BLK;
    int s = 0;
    #pragma unroll
    for (int q = 0; q < 4; q++) {
        int i = base + t * 4 + q;
        if (i < N) s += g_cnt[i];
    }
    sdata[t] = s;
    __syncthreads();
    #pragma unroll
    for (int o = 128; o > 0; o >>= 1) {
        if (t < o) sdata[t] += sdata[t + o];
        __syncthreads();
    }
    if (t == 0) g_bsum[blockIdx.x] = sdata[0];
}

__global__ void scan_write_kernel(int N, int E) {
    __shared__ int ssum[256];
    __shared__ int sb[128];
    __shared__ int sbase;
    const int b = blockIdx.x, t = threadIdx.x;
    if (t < gridDim.x && t < 128) sb[t] = g_bsum[t];
    __syncthreads();
    if (t == 0) {
        int a = 0;
        for (int j = 0; j < b; j++) a += sb[j];
        sbase = a;
        if (b == 0) g_off[N] = E;
    }
    const int base = b * SCAN_BLK;
    int v[4];
    int local = 0;
    #pragma unroll
    for (int q = 0; q < 4; q++) {
        int i = base + t * 4 + q;
        v[q] = (i < N) ? g_cnt[i] : 0;
        local += v[q];
    }
    ssum[t] = local;
    __syncthreads();
    for (int o = 1; o < 256; o <<= 1) {
        int x = (t >= o) ? ssum[t - o] : 0;
        __syncthreads();
        ssum[t] += x;
        __syncthreads();
    }
    int excl = sbase + ssum[t] - local;
    #pragma unroll
    for (int q = 0; q < 4; q++) {
        int i = base + t * 4 + q;
        if (i < N) { g_off[i] = excl; g_cnt[i] = excl; }   // g_cnt becomes cursor
        excl += v[q];
    }
}

__global__ void fill_kernel(const int* __restrict__ src,
                            const int* __restrict__ dst, int E) {
    int base = (blockIdx.x * blockDim.x + threadIdx.x) * 4;
    if (base + 3 < E) {
        int4 s4 = *reinterpret_cast<const int4*>(src + base);
        int4 d4 = *reinterpret_cast<const int4*>(dst + base);
        int p;
        p = atomicAdd(&g_cnt[d4.x], 1); g_esrc[p] = s4.x;
        p = atomicAdd(&g_cnt[d4.y], 1); g_esrc[p] = s4.y;
        p = atomicAdd(&g_cnt[d4.z], 1); g_esrc[p] = s4.z;
        p = atomicAdd(&g_cnt[d4.w], 1); g_esrc[p] = s4.w;
    } else {
        for (int e = base; e < E; e++) {
            int p = atomicAdd(&g_cnt[dst[e]], 1);
            g_esrc[p] = src[e];
        }
    }
}

// ---------------------------------------------------------------------------
// GEMM: proj = relu(h @ W^T) -> fp16. Single-pass fp16 HMMA, fp32 accum.
//   CTA: 128 rows x 128 out x 128 k, 8 warps = 2(m) x 4(n), warp tile 64x32.
//   h staging uses LINEAR float4 indexing -> consecutive lanes contiguous
//   (nL=4 lines/warp-LDG instead of 32; 8x fewer L1 wavefronts).
// ---------------------------------------------------------------------------
#define LDB 136
#define ROWB (LDB * 2)
#define GEMM_SMEM (128 * ROWB)     // 34816 bytes

__global__ __launch_bounds__(256, 2)
void gemm_relu_hmma_kernel(const float* __restrict__ h, int N)
{
    extern __shared__ char smem[];
    const uint32_t sbase = smem_to_u32(smem);
    const int tid  = threadIdx.x;
    const int lane = tid & 31;
    const int wid  = tid >> 5;
    const int warp_m = wid & 1;
    const int warp_n = wid >> 1;
    const int rowBase = blockIdx.x * 128;

    // ---- stage h tile as fp16 (coalesced: linear float4 index) ----
    {
        const float4* hsrc = reinterpret_cast<const float4*>(h)
                           + (size_t)rowBase * 32;        // 32 float4 per row
        #pragma unroll
        for (int q = 0; q < 16; q++) {
            int f  = q * 256 + tid;        // float4 index in tile, 0..4095
            int r  = f >> 5;               // tile row
            int c4 = f & 31;               // float4 column
            int gr = rowBase + r;
            float4 v = (gr < N) ? __ldg(&hsrc[f])
                                : make_float4(0.f, 0.f, 0.f, 0.f);
            *reinterpret_cast<uint2*>(smem + r * ROWB + c4 * 8) =
                make_uint2(pack_h2(v.x, v.y), pack_h2(v.z, v.w));
        }
    }
    __syncthreads();

    float acc[4][4][4];
    #pragma unroll
    for (int mi = 0; mi < 4; mi++)
        #pragma unroll
        for (int ni = 0; ni < 4; ni++)
            #pragma unroll
            for (int r = 0; r < 4; r++)
                acc[mi][ni][r] = 0.0f;

    const int lrow = lane & 15;
    const int lk8  = (lane >> 4) << 3;
    const uint32_t wrowoff =
        (uint32_t)(warp_n * 32 + (lane >> 2)) * 64 + (lane & 3);

    #pragma unroll
    for (int ks = 0; ks < 8; ks++) {
        const int k0 = ks * 16;
        uint32_t a[4][4];
        #pragma unroll
        for (int mi = 0; mi < 4; mi++) {
            uint32_t addr = sbase
                + (uint32_t)(warp_m * 64 + mi * 16 + lrow) * ROWB
                + (uint32_t)(k0 + lk8) * 2;
            LDMATRIX_X4(a[mi][0], a[mi][1], a[mi][2], a[mi][3], addr);
        }
        #pragma unroll
        for (int ni = 0; ni < 4; ni++) {
            const uint32_t* wrow = g_Whi + wrowoff + (uint32_t)ni * 8 * 64;
            uint32_t b[2];
            b[0] = wrow[ks * 8];
            b[1] = wrow[ks * 8 + 4];
            #pragma unroll
            for (int mi = 0; mi < 4; mi++)
                MMA_F16(acc[mi][ni], a[mi], b);
        }
    }

    // ---- epilogue: ReLU + fp16 store ----
    const int erow = lane >> 2;
    const int ecol = (lane & 3) * 2;
    #pragma unroll
    for (int mi = 0; mi < 4; mi++) {
        const int row0 = rowBase + warp_m * 64 + mi * 16 + erow;
        #pragma unroll
        for (int ni = 0; ni < 4; ni++) {
            const int col = warp_n * 32 + ni * 8 + ecol;
            if (row0 < N) {
                __half2 hv = __floats2half2_rn(fmaxf(acc[mi][ni][0], 0.0f),
                                               fmaxf(acc[mi][ni][1], 0.0f));
                *reinterpret_cast<__half2*>(
                    g_projh + (size_t)row0 * DIM + col) = hv;
            }
            if (row0 + 8 < N) {
                __half2 hv = __floats2half2_rn(fmaxf(acc[mi][ni][2], 0.0f),
                                               fmaxf(acc[mi][ni][3], 0.0f));
                *reinterpret_cast<__half2*>(
                    g_projh + (size_t)(row0 + 8) * DIM + col) = hv;
            }
        }
    }
}

// ---------------------------------------------------------------------------
// Persistent gather (R12-proven): out[d] = sum over CSR bucket of projh[src]
// 16 lanes per dst (uint4 = 8 fp16 per lane). MLP=8 row loads per batch;
// indices past end clamp to the all-zero pad row (L1-hot, nearly free).
// Self-cleans g_cnt[d]=0 so the next call's histogram starts from zeros
// (removes the memset node from the prep chain).
// ---------------------------------------------------------------------------
__device__ __forceinline__ void acc_row(float acc[8], uint4 r) {
    const __half2* hp = reinterpret_cast<const __half2*>(&r);
    #pragma unroll
    for (int j = 0; j < 4; j++) {
        float2 f = __half22float2(hp[j]);
        acc[j * 2 + 0] += f.x;
        acc[j * 2 + 1] += f.y;
    }
}

#define GATHER_BLOCKS 1184   // 8 per SM x 148 SMs

__global__ __launch_bounds__(256)
void gather_kernel(float* __restrict__ out, int N)
{
    const int l16    = threadIdx.x & 15;
    const int grp0   = (blockIdx.x * blockDim.x + threadIdx.x) >> 4;
    const int stride = (GATHER_BLOCKS * 256) >> 4;

    const uint4* projv = reinterpret_cast<const uint4*>(g_projh) + l16;

    for (int d = grp0; d < N; d += stride) {
        const int start = __ldg(&g_off[d]);
        const int end   = __ldg(&g_off[d + 1]);

        float acc[8];
        #pragma unroll
        for (int j = 0; j < 8; j++) acc[j] = 0.0f;

        for (int i = start; i < end; i += 8) {
            int idx[8];
            #pragma unroll
            for (int j = 0; j < 8; j++)
                idx[j] = (i + j < end) ? __ldg(&g_esrc[i + j]) : MAX_NODES;
            uint4 r[8];
            #pragma unroll
            for (int j = 0; j < 8; j++)
                r[j] = __ldg(&projv[(size_t)idx[j] * 16]);
            #pragma unroll
            for (int j = 0; j < 8; j++)
                acc_row(acc, r[j]);
        }

        float* op = out + (size_t)d * DIM + l16 * 8;
        __stcs(reinterpret_cast<float4*>(op),
               make_float4(acc[0], acc[1], acc[2], acc[3]));
        __stcs(reinterpret_cast<float4*>(op + 4),
               make_float4(acc[4], acc[5], acc[6], acc[7]));

        if (l16 == 0) g_cnt[d] = 0;   // self-clean for next call's histogram
    }
}

// ---------------------------------------------------------------------------
// Launch: s2 runs wprep(+pad zero) + GEMM; stream 0 runs CSR build.
// No g_cnt memset: zero-init covers call 1; gather self-cleans thereafter.
// ---------------------------------------------------------------------------
extern "C" void kernel_launch(void* const* d_in, const int* in_sizes, int n_in,
                              void* d_out, int out_size)
{
    const float* h   = (const float*)d_in[0];
    const float* W   = (const float*)d_in[1];
    const int*   src = (const int*)d_in[2];
    const int*   dst = (const int*)d_in[3];
    float*       out = (float*)d_out;

    const int N = in_sizes[0] / DIM;
    const int E = in_sizes[2];

    static cudaStream_t s2 = nullptr;
    static cudaEvent_t evFork = nullptr, evJoin = nullptr;
    if (!s2) {
        cudaStreamCreateWithFlags(&s2, cudaStreamNonBlocking);
        cudaEventCreateWithFlags(&evFork, cudaEventDisableTiming);
        cudaEventCreateWithFlags(&evJoin, cudaEventDisableTiming);
        cudaFuncSetAttribute(gemm_relu_hmma_kernel,
                             cudaFuncAttributeMaxDynamicSharedMemorySize,
                             GEMM_SMEM);
    }

    // ---- fork immediately: s2 = wprep(+pad zero) + GEMM ----
    cudaEventRecord(evFork, 0);
    cudaStreamWaitEvent(s2, evFork, 0);

    wprep_kernel<<<32, 256, 0, s2>>>(W);
    gemm_relu_hmma_kernel<<<(N + 127) / 128, 256, GEMM_SMEM, s2>>>(h, N);

    // ---- stream 0: CSR build (g_cnt already zero) ----
    hist_kernel<<<(E / 4 + 255) / 256 + 1, 256>>>(dst, E);
    const int NB = (N + SCAN_BLK - 1) / SCAN_BLK;
    scan_reduce_kernel<<<NB, 256>>>(N);
    scan_write_kernel<<<NB, 256>>>(N, E);
    fill_kernel<<<(E / 4 + 255) / 256 + 1, 256>>>(src, dst, E);

    // ---- join ----
    cudaEventRecord(evJoin, s2);
    cudaStreamWaitEvent(0, evJoin, 0);

    // Persistent gather (R12 layout) + g_cnt self-clean
    gather_kernel<<<GATHER_BLOCKS, 256>>>(out, N);
}

// round 17
// speedup vs baseline: 1.3288x; 1.0092x over previous
#include <cuda_runtime.h>
#include <cuda_bf16.h>
#include <cuda_fp16.h>
#include <cstdint>

#define DIM        128
#define MAX_NODES  100000
#define MAX_EDGES  800000

// ---------------------------------------------------------------------------
// Static device scratch (no allocations allowed)
// g_projh has one extra all-zero row at index MAX_NODES (gather pad target).
// g_cnt relies on static zero-init for the FIRST call; the gather kernel
// re-zeroes it at the end of every call (self-cleaning, deterministic).
// ---------------------------------------------------------------------------
__device__ __half   g_projh[(size_t)(MAX_NODES + 1) * DIM];
__device__ uint32_t g_Whi[DIM * DIM / 2];               // fp16x2 [n][k/2]
__device__ int      g_cnt[MAX_NODES];                   // degree, then cursor
__device__ int      g_off[MAX_NODES + 1];               // CSR offsets (by dst)
__device__ int      g_bsum[128];                        // scan block sums
__device__ int      g_esrc[MAX_EDGES];                  // src grouped by dst

// ---------------------------------------------------------------------------
// helpers
// ---------------------------------------------------------------------------
__device__ __forceinline__ uint32_t smem_to_u32(const void* smem_ptr) {
    uint32_t addr;
    asm("{ .reg .u64 tmp; cvta.to.shared.u64 tmp, %1; cvt.u32.u64 %0, tmp; }"
        : "=r"(addr) : "l"(smem_ptr));
    return addr;
}

#define LDMATRIX_X4(r0, r1, r2, r3, addr) \
    asm volatile("ldmatrix.sync.aligned.m8n8.x4.shared.b16 {%0,%1,%2,%3}, [%4];" \
        : "=r"(r0), "=r"(r1), "=r"(r2), "=r"(r3) : "r"(addr))

#define MMA_F16(c, a, b) \
    asm volatile("mma.sync.aligned.m16n8k16.row.col.f32.f16.f16.f32 " \
        "{%0,%1,%2,%3}, {%4,%5,%6,%7}, {%8,%9}, {%0,%1,%2,%3};" \
        : "+f"((c)[0]), "+f"((c)[1]), "+f"((c)[2]), "+f"((c)[3]) \
        : "r"((a)[0]), "r"((a)[1]), "r"((a)[2]), "r"((a)[3]), \
          "r"((b)[0]), "r"((b)[1]))

__device__ __forceinline__ uint32_t pack_h2(float a, float b) {
    __half2 h = __floats2half2_rn(a, b);
    return *reinterpret_cast<uint32_t*>(&h);
}

// ---------------------------------------------------------------------------
// W precompute: W[n][k] fp32 -> fp16 packed pairs [n][k/2].
// Also zeroes the proj pad row (block 0).
// ---------------------------------------------------------------------------
__global__ void wprep_kernel(const float* __restrict__ W) {
    int idx = blockIdx.x * blockDim.x + threadIdx.x;      // 0..8191
    if (blockIdx.x == 0 && threadIdx.x < 64)
        reinterpret_cast<uint32_t*>(g_projh)[(size_t)MAX_NODES * 64 + threadIdx.x] = 0;
    if (idx >= DIM * DIM / 2) return;
    int n  = idx >> 6;
    int kp = idx & 63;
    float2 w = *reinterpret_cast<const float2*>(W + (size_t)n * DIM + kp * 2);
    g_Whi[idx] = pack_h2(w.x, w.y);
}

// ---------------------------------------------------------------------------
// CSR build: histogram -> scan -> fill (hist/fill vectorized 4 edges/thread)
// ---------------------------------------------------------------------------
__global__ void hist_kernel(const int* __restrict__ dst, int E) {
    int base = (blockIdx.x * blockDim.x + threadIdx.x) * 4;
    if (base + 3 < E) {
        int4 d4 = *reinterpret_cast<const int4*>(dst + base);
        atomicAdd(&g_cnt[d4.x], 1);
        atomicAdd(&g_cnt[d4.y], 1);
        atomicAdd(&g_cnt[d4.z], 1);
        atomicAdd(&g_cnt[d4.w], 1);
    } else {
        for (int e = base; e < E; e++) atomicAdd(&g_cnt[dst[e]], 1);
    }
}

#define SCAN_BLK 1024
__global__ void scan_reduce_kernel(int N) {
    __shared__ int sdata[256];
    const int t    = threadIdx.x;
    const int base = blockIdx.x * SCAN_BLK;
    int s = 0;
    #pragma unroll
    for (int q = 0; q < 4; q++) {
        int i = base + t * 4 + q;
        if (i < N) s += g_cnt[i];
    }
    sdata[t] = s;
    __syncthreads();
    #pragma unroll
    for (int o = 128; o > 0; o >>= 1) {
        if (t < o) sdata[t] += sdata[t + o];
        __syncthreads();
    }
    if (t == 0) g_bsum[blockIdx.x] = sdata[0];
}

__global__ void scan_write_kernel(int N, int E) {
    __shared__ int ssum[256];
    __shared__ int sb[128];
    __shared__ int sbase;
    const int b = blockIdx.x, t = threadIdx.x;
    if (t < gridDim.x && t < 128) sb[t] = g_bsum[t];
    __syncthreads();
    if (t == 0) {
        int a = 0;
        for (int j = 0; j < b; j++) a += sb[j];
        sbase = a;
        if (b == 0) g_off[N] = E;
    }
    const int base = b * SCAN_BLK;
    int v[4];
    int local = 0;
    #pragma unroll
    for (int q = 0; q < 4; q++) {
        int i = base + t * 4 + q;
        v[q] = (i < N) ? g_cnt[i] : 0;
        local += v[q];
    }
    ssum[t] = local;
    __syncthreads();
    for (int o = 1; o < 256; o <<= 1) {
        int x = (t >= o) ? ssum[t - o] : 0;
        __syncthreads();
        ssum[t] += x;
        __syncthreads();
    }
    int excl = sbase + ssum[t] - local;
    #pragma unroll
    for (int q = 0; q < 4; q++) {
        int i = base + t * 4 + q;
        if (i < N) { g_off[i] = excl; g_cnt[i] = excl; }   // g_cnt becomes cursor
        excl += v[q];
    }
}

__global__ void fill_kernel(const int* __restrict__ src,
                            const int* __restrict__ dst, int E) {
    int base = (blockIdx.x * blockDim.x + threadIdx.x) * 4;
    if (base + 3 < E) {
        int4 s4 = *reinterpret_cast<const int4*>(src + base);
        int4 d4 = *reinterpret_cast<const int4*>(dst + base);
        int p;
        p = atomicAdd(&g_cnt[d4.x], 1); g_esrc[p] = s4.x;
        p = atomicAdd(&g_cnt[d4.y], 1); g_esrc[p] = s4.y;
        p = atomicAdd(&g_cnt[d4.z], 1); g_esrc[p] = s4.z;
        p = atomicAdd(&g_cnt[d4.w], 1); g_esrc[p] = s4.w;
    } else {
        for (int e = base; e < E; e++) {
            int p = atomicAdd(&g_cnt[dst[e]], 1);
            g_esrc[p] = src[e];
        }
    }
}

// ---------------------------------------------------------------------------
// GEMM: proj = relu(h @ W^T) -> fp16. Single-pass fp16 HMMA, fp32 accum.
//   CTA: 128 rows x 128 out x 128 k, 8 warps = 2(m) x 4(n), warp tile 64x32.
//   h staging uses LINEAR float4 indexing (coalesced; nL=4 lines/warp-LDG).
// ---------------------------------------------------------------------------
#define LDB 136
#define ROWB (LDB * 2)
#define GEMM_SMEM (128 * ROWB)     // 34816 bytes

__global__ __launch_bounds__(256, 2)
void gemm_relu_hmma_kernel(const float* __restrict__ h, int N)
{
    extern __shared__ char smem[];
    const uint32_t sbase = smem_to_u32(smem);
    const int tid  = threadIdx.x;
    const int lane = tid & 31;
    const int wid  = tid >> 5;
    const int warp_m = wid & 1;
    const int warp_n = wid >> 1;
    const int rowBase = blockIdx.x * 128;

    // ---- stage h tile as fp16 (coalesced: linear float4 index) ----
    {
        const float4* hsrc = reinterpret_cast<const float4*>(h)
                           + (size_t)rowBase * 32;        // 32 float4 per row
        #pragma unroll
        for (int q = 0; q < 16; q++) {
            int f  = q * 256 + tid;        // float4 index in tile, 0..4095
            int r  = f >> 5;               // tile row
            int c4 = f & 31;               // float4 column
            int gr = rowBase + r;
            float4 v = (gr < N) ? __ldg(&hsrc[f])
                                : make_float4(0.f, 0.f, 0.f, 0.f);
            *reinterpret_cast<uint2*>(smem + r * ROWB + c4 * 8) =
                make_uint2(pack_h2(v.x, v.y), pack_h2(v.z, v.w));
        }
    }
    __syncthreads();

    float acc[4][4][4];
    #pragma unroll
    for (int mi = 0; mi < 4; mi++)
        #pragma unroll
        for (int ni = 0; ni < 4; ni++)
            #pragma unroll
            for (int r = 0; r < 4; r++)
                acc[mi][ni][r] = 0.0f;

    const int lrow = lane & 15;
    const int lk8  = (lane >> 4) << 3;
    const uint32_t wrowoff =
        (uint32_t)(warp_n * 32 + (lane >> 2)) * 64 + (lane & 3);

    #pragma unroll
    for (int ks = 0; ks < 8; ks++) {
        const int k0 = ks * 16;
        uint32_t a[4][4];
        #pragma unroll
        for (int mi = 0; mi < 4; mi++) {
            uint32_t addr = sbase
                + (uint32_t)(warp_m * 64 + mi * 16 + lrow) * ROWB
                + (uint32_t)(k0 + lk8) * 2;
            LDMATRIX_X4(a[mi][0], a[mi][1], a[mi][2], a[mi][3], addr);
        }
        #pragma unroll
        for (int ni = 0; ni < 4; ni++) {
            const uint32_t* wrow = g_Whi + wrowoff + (uint32_t)ni * 8 * 64;
            uint32_t b[2];
            b[0] = wrow[ks * 8];
            b[1] = wrow[ks * 8 + 4];
            #pragma unroll
            for (int mi = 0; mi < 4; mi++)
                MMA_F16(acc[mi][ni], a[mi], b);
        }
    }

    // ---- epilogue: ReLU + fp16 store ----
    const int erow = lane >> 2;
    const int ecol = (lane & 3) * 2;
    #pragma unroll
    for (int mi = 0; mi < 4; mi++) {
        const int row0 = rowBase + warp_m * 64 + mi * 16 + erow;
        #pragma unroll
        for (int ni = 0; ni < 4; ni++) {
            const int col = warp_n * 32 + ni * 8 + ecol;
            if (row0 < N) {
                __half2 hv = __floats2half2_rn(fmaxf(acc[mi][ni][0], 0.0f),
                                               fmaxf(acc[mi][ni][1], 0.0f));
                *reinterpret_cast<__half2*>(
                    g_projh + (size_t)row0 * DIM + col) = hv;
            }
            if (row0 + 8 < N) {
                __half2 hv = __floats2half2_rn(fmaxf(acc[mi][ni][2], 0.0f),
                                               fmaxf(acc[mi][ni][3], 0.0f));
                *reinterpret_cast<__half2*>(
                    g_projh + (size_t)(row0 + 8) * DIM + col) = hv;
            }
        }
    }
}

// ---------------------------------------------------------------------------
// Persistent gather: out[d] = sum over CSR bucket of projh[src]
// 16 lanes per dst (uint4 = 8 fp16 per lane).
// Indices loaded COALESCED: lane l fetches edge start+l -> one LDG covers 16
// edges (2 row batches); values broadcast via width-16 shfl with half-warp
// masks (the warp's two groups serve different dsts and may diverge).
// Row batches of 8 (MLP=8). Out-of-range edges clamp to the zero pad row.
// Accumulation order per dst is unchanged -> bit-identical results.
// Self-cleans g_cnt[d]=0 (removes memset node from next call's prep).
// ---------------------------------------------------------------------------
__device__ __forceinline__ void acc_row(float acc[8], uint4 r) {
    const __half2* hp = reinterpret_cast<const __half2*>(&r);
    #pragma unroll
    for (int j = 0; j < 4; j++) {
        float2 f = __half22float2(hp[j]);
        acc[j * 2 + 0] += f.x;
        acc[j * 2 + 1] += f.y;
    }
}

#define GATHER_BLOCKS 1184   // 8 per SM x 148 SMs

__global__ __launch_bounds__(256)
void gather_kernel(float* __restrict__ out, int N)
{
    const int l16    = threadIdx.x & 15;
    const uint32_t shmask = 0xFFFFu << (threadIdx.x & 16);  // my half-warp
    const int grp0   = (blockIdx.x * blockDim.x + threadIdx.x) >> 4;
    const int stride = (GATHER_BLOCKS * 256) >> 4;

    const uint4* projv = reinterpret_cast<const uint4*>(g_projh) + l16;

    for (int d = grp0; d < N; d += stride) {
        const int start = __ldg(&g_off[d]);
        const int end   = __ldg(&g_off[d + 1]);

        float acc[8];
        #pragma unroll
        for (int j = 0; j < 8; j++) acc[j] = 0.0f;

        for (int i = start; i < end; i += 16) {
            // one coalesced idx load covers up to 16 edges
            const int li = i + l16;
            const int myidx = (li < end) ? __ldg(&g_esrc[li]) : MAX_NODES;

            // batch 1: edges i..i+7
            uint4 r[8];
            #pragma unroll
            for (int j = 0; j < 8; j++) {
                int s = __shfl_sync(shmask, myidx, j, 16);
                r[j] = __ldg(&projv[(size_t)s * 16]);
            }
            #pragma unroll
            for (int j = 0; j < 8; j++)
                acc_row(acc, r[j]);

            // batch 2: edges i+8..i+15 (skipped when bucket chunk <= 8)
            if (i + 8 < end) {
                #pragma unroll
                for (int j = 0; j < 8; j++) {
                    int s = __shfl_sync(shmask, myidx, 8 + j, 16);
                    r[j] = __ldg(&projv[(size_t)s * 16]);
                }
                #pragma unroll
                for (int j = 0; j < 8; j++)
                    acc_row(acc, r[j]);
            }
        }

        float* op = out + (size_t)d * DIM + l16 * 8;
        __stcs(reinterpret_cast<float4*>(op),
               make_float4(acc[0], acc[1], acc[2], acc[3]));
        __stcs(reinterpret_cast<float4*>(op + 4),
               make_float4(acc[4], acc[5], acc[6], acc[7]));

        if (l16 == 0) g_cnt[d] = 0;   // self-clean for next call's histogram
    }
}

// ---------------------------------------------------------------------------
// Launch: s2 runs wprep(+pad zero) + GEMM; stream 0 runs CSR build.
// No g_cnt memset: zero-init covers call 1; gather self-cleans thereafter.
// ---------------------------------------------------------------------------
extern "C" void kernel_launch(void* const* d_in, const int* in_sizes, int n_in,
                              void* d_out, int out_size)
{
    const float* h   = (const float*)d_in[0];
    const float* W   = (const float*)d_in[1];
    const int*   src = (const int*)d_in[2];
    const int*   dst = (const int*)d_in[3];
    float*       out = (float*)d_out;

    const int N = in_sizes[0] / DIM;
    const int E = in_sizes[2];

    static cudaStream_t s2 = nullptr;
    static cudaEvent_t evFork = nullptr, evJoin = nullptr;
    if (!s2) {
        cudaStreamCreateWithFlags(&s2, cudaStreamNonBlocking);
        cudaEventCreateWithFlags(&evFork, cudaEventDisableTiming);
        cudaEventCreateWithFlags(&evJoin, cudaEventDisableTiming);
        cudaFuncSetAttribute(gemm_relu_hmma_kernel,
                             cudaFuncAttributeMaxDynamicSharedMemorySize,
                             GEMM_SMEM);
    }

    // ---- fork immediately: s2 = wprep(+pad zero) + GEMM ----
    cudaEventRecord(evFork, 0);
    cudaStreamWaitEvent(s2, evFork, 0);

    wprep_kernel<<<32, 256, 0, s2>>>(W);
    gemm_relu_hmma_kernel<<<(N + 127) / 128, 256, GEMM_SMEM, s2>>>(h, N);

    // ---- stream 0: CSR build (g_cnt already zero) ----
    hist_kernel<<<(E / 4 + 255) / 256 + 1, 256>>>(dst, E);
    const int NB = (N + SCAN_BLK - 1) / SCAN_BLK;
    scan_reduce_kernel<<<NB, 256>>>(N);
    scan_write_kernel<<<NB, 256>>>(N, E);
    fill_kernel<<<(E / 4 + 255) / 256 + 1, 256>>>(src, dst, E);

    // ---- join ----
    cudaEventRecord(evJoin, s2);
    cudaStreamWaitEvent(0, evJoin, 0);

    // Persistent gather (coalesced idx) + g_cnt self-clean
    gather_kernel<<<GATHER_BLOCKS, 256>>>(out, N);
}